// round 7
// baseline (speedup 1.0000x reference)
#include <cuda_runtime.h>
#include <math.h>

// ---------------- constants ----------------
#define EPSL      1e-7f
#define POS_THRF  0.5f
#define NEG_THRF  0.4f
#define ALPHA_F   0.25f
#define K4PI2     0.40528473456935109f   // 4 / pi^2

#define MAX_NA  806400    // N*A = 32*25200
#define MAX_NP  8192      // N*P
#define MAX_N   64
#define PMAX    128

// ---------------- scratch (static, no allocation) ----------------
__device__ int                g_state[MAX_NA];
__device__ int                g_tidx[MAX_NA];
__device__ unsigned long long g_gtpacked[MAX_NP];
__device__ int                g_poscnt[MAX_N];
__device__ double             g_sums[3];

// ---------------- kernel 0: zero scratch that needs it ----------------
__global__ void init_kernel(int NP, int N) {
    int i = blockIdx.x * blockDim.x + threadIdx.x;
    if (i < NP) g_gtpacked[i] = 0ull;
    if (i < N)  g_poscnt[i]   = 0;
    if (i < 3)  g_sums[i]     = 0.0;
}

// ---------------- kernel 1: max-IoU assigner ----------------
// 4 anchors per thread, 128 threads/block -> 512 anchors per block.
#define BLK_A 128
#define KPT   4

__global__ void assign_kernel(const float* __restrict__ bbox_true,
                              const float* __restrict__ anchors,
                              int N, int A, int P) {
    __shared__ float4             gbox[PMAX];
    __shared__ float              garea[PMAX];
    __shared__ int                gvalid[PMAX];
    __shared__ unsigned long long gts[PMAX];

    const int n   = blockIdx.y;
    const int tid = threadIdx.x;
    const int lane = tid & 31;

    for (int p = tid; p < P; p += BLK_A) {
        float4 b = ((const float4*)bbox_true)[(long)n * P + p];
        gbox[p]   = b;
        garea[p]  = (b.z - b.x) * (b.w - b.y);
        gvalid[p] = (b.x > 0.f) || (b.y > 0.f) || (b.z > 0.f) || (b.w > 0.f);
        gts[p]    = 0ull;
    }
    __syncthreads();

    float ax1[KPT], ay1[KPT], ax2[KPT], ay2[KPT], aA[KPT], best[KPT];
    int   bestp[KPT], aidx[KPT];

#pragma unroll
    for (int k = 0; k < KPT; k++) {
        int a = blockIdx.x * (BLK_A * KPT) + k * BLK_A + tid;
        aidx[k]  = a;
        best[k]  = -1.0f;
        bestp[k] = 0;
        if (a < A) {
            float4 b = ((const float4*)anchors)[a];
            ax1[k] = b.x; ay1[k] = b.y; ax2[k] = b.z; ay2[k] = b.w;
            aA[k]  = (b.z - b.x) * (b.w - b.y);
        } else {
            // degenerate box: inter=0, area=0 -> iou = 0, never pushed to gt side
            ax1[k] = 4.0f; ay1[k] = 4.0f; ax2[k] = 4.0f; ay2[k] = 4.0f;
            aA[k]  = 0.0f;
        }
    }

    for (int p = 0; p < P; p++) {
        if (!gvalid[p]) continue;           // uniform branch per block
        float4 g  = gbox[p];
        float  gA = garea[p];

        float    m  = 0.0f;                 // only iou>0 matters for gt side
        unsigned ma = 0u;
#pragma unroll
        for (int k = 0; k < KPT; k++) {
            float iw = fminf(ax2[k], g.z) - fmaxf(ax1[k], g.x);
            float ih = fminf(ay2[k], g.w) - fmaxf(ay1[k], g.y);
            iw = fmaxf(iw, 0.0f); ih = fmaxf(ih, 0.0f);
            float inter = iw * ih;
            float iou = inter / (aA[k] + gA - inter + EPSL);
            if (iou > best[k]) { best[k] = iou; bestp[k] = p; }   // strict > : first-occurrence argmax over p
            if (iou > m)       { m = iou; ma = (unsigned)aidx[k]; } // strict > : smallest anchor idx on tie
        }

        unsigned long long packed = 0ull;
        if (m > 0.0f)
            packed = ((unsigned long long)__float_as_uint(m) << 32)
                   | (unsigned long long)(~ma);   // ~a: larger packed => smaller anchor idx on iou tie
        if (__ballot_sync(0xffffffffu, packed != 0ull)) {
#pragma unroll
            for (int off = 16; off > 0; off >>= 1) {
                unsigned long long o = __shfl_down_sync(0xffffffffu, packed, off);
                if (o > packed) packed = o;
            }
            if (lane == 0 && packed) atomicMax(&gts[p], packed);
        }
    }
    __syncthreads();

#pragma unroll
    for (int k = 0; k < KPT; k++) {
        int a = aidx[k];
        if (a < A) {
            int s = (best[k] >= POS_THRF) ? 1 : ((best[k] < NEG_THRF) ? -1 : 0);
            long idx = (long)n * A + a;
            g_state[idx] = s;
            g_tidx[idx]  = bestp[k];
        }
    }
    for (int p = tid; p < P; p += BLK_A)
        if (gts[p]) atomicMax(&g_gtpacked[(long)n * P + p], gts[p]);
}

// ---------------- kernel 2: low-quality match override ----------------
// one thread per image, serial over p (preserves scatter ordering: last p wins)
__global__ void lowq_kernel(int N, int A, int P) {
    int n = blockIdx.x * blockDim.x + threadIdx.x;
    if (n >= N) return;
    for (int p = 0; p < P; p++) {
        unsigned long long v = g_gtpacked[(long)n * P + p];
        if (v) {  // nonzero => valid gt with gt_max > 0 => lowq
            unsigned a = ~(unsigned)(v & 0xffffffffull);
            long idx = (long)n * A + a;
            g_state[idx] = 1;
            g_tidx[idx]  = p;
        }
    }
}

// ---------------- kernel 3: losses ----------------
#define BLK_L 256

__global__ void loss_kernel(const float* __restrict__ conf_pred,
                            const float* __restrict__ logit_pred,
                            const float* __restrict__ bbox_pred,
                            const float* __restrict__ bbox_true,
                            const float* __restrict__ y_true,
                            int N, int A, int P, int C) {
    const int n = blockIdx.y;
    const int a = blockIdx.x * BLK_L + threadIdx.x;

    float score = 0.0f, cls = 0.0f, bb = 0.0f;
    int   cnt = 0;

    if (a < A) {
        long idx = (long)n * A + a;
        int  s   = g_state[idx];
        if (s) {
            float cp = conf_pred[idx];
            cp = fminf(fmaxf(cp, EPSL), 1.0f - EPSL);
            score = (s == 1) ? -logf(cp) : -logf(1.0f - cp);
        }
        if (s == 1) {
            cnt = 1;
            int t = g_tidx[idx];
            float4 bt = ((const float4*)bbox_true)[(long)n * P + t];
            float4 bp = ((const float4*)bbox_pred)[idx];
            // CIoU
            float ix1 = fmaxf(bt.x, bp.x), iy1 = fmaxf(bt.y, bp.y);
            float ix2 = fminf(bt.z, bp.z), iy2 = fminf(bt.w, bp.w);
            float inter = fmaxf(ix2 - ix1, 0.0f) * fmaxf(iy2 - iy1, 0.0f);
            float wt = bt.z - bt.x, ht = bt.w - bt.y;
            float wp = bp.z - bp.x, hp = bp.w - bp.y;
            float uni = wt * ht + wp * hp - inter + EPSL;
            float iou = inter / uni;
            float cw = fmaxf(bt.z, bp.z) - fminf(bt.x, bp.x);
            float ch = fmaxf(bt.w, bp.w) - fminf(bt.y, bp.y);
            float c2 = cw * cw + ch * ch + EPSL;
            float dx = bt.x + bt.z - bp.x - bp.z;
            float dy = bt.y + bt.w - bp.y - bp.w;
            float rho2 = (dx * dx + dy * dy) * 0.25f;
            float da = atanf(wt / (ht + EPSL)) - atanf(wp / (hp + EPSL));
            float v = K4PI2 * da * da;
            float alpha = v / (1.0f - iou + v + EPSL);
            bb = 1.0f - iou + rho2 / c2 + alpha * v;

            // focal class loss (only positives contribute)
            const float* yt = y_true     + ((long)n * P + t) * C;
            const float* lp = logit_pred + idx * (long)C;
            for (int c = 0; c < C; c++) {
                float q  = fminf(fmaxf(lp[c], EPSL), 1.0f - EPSL);
                float tl = yt[c];
                float pt = tl * q + (1.0f - tl) * (1.0f - q);
                float at = tl * ALPHA_F + (1.0f - tl) * (1.0f - ALPHA_F);
                float om = 1.0f - pt;
                cls += -at * om * om * logf(pt);
            }
        }
    }

    // block reduction (all threads participate)
    const int lane = threadIdx.x & 31;
    const int w    = threadIdx.x >> 5;
#pragma unroll
    for (int off = 16; off > 0; off >>= 1) {
        score += __shfl_down_sync(0xffffffffu, score, off);
        cls   += __shfl_down_sync(0xffffffffu, cls,   off);
        bb    += __shfl_down_sync(0xffffffffu, bb,    off);
        cnt   += __shfl_down_sync(0xffffffffu, cnt,   off);
    }
    __shared__ float s0[BLK_L / 32], s1[BLK_L / 32], s2[BLK_L / 32];
    __shared__ int   s3[BLK_L / 32];
    if (lane == 0) { s0[w] = score; s1[w] = cls; s2[w] = bb; s3[w] = cnt; }
    __syncthreads();
    if (w == 0) {
        const int nw = BLK_L / 32;
        float v0 = (lane < nw) ? s0[lane] : 0.0f;
        float v1 = (lane < nw) ? s1[lane] : 0.0f;
        float v2 = (lane < nw) ? s2[lane] : 0.0f;
        int   v3 = (lane < nw) ? s3[lane] : 0;
#pragma unroll
        for (int off = 16; off > 0; off >>= 1) {
            v0 += __shfl_down_sync(0xffffffffu, v0, off);
            v1 += __shfl_down_sync(0xffffffffu, v1, off);
            v2 += __shfl_down_sync(0xffffffffu, v2, off);
            v3 += __shfl_down_sync(0xffffffffu, v3, off);
        }
        if (lane == 0) {
            if (v0 != 0.0f) atomicAdd(&g_sums[0], (double)v0);
            if (v1 != 0.0f) atomicAdd(&g_sums[1], (double)v1);
            if (v2 != 0.0f) atomicAdd(&g_sums[2], (double)v2);
            if (v3)         atomicAdd(&g_poscnt[n], v3);
        }
    }
}

// ---------------- kernel 4: finalize ----------------
__global__ void final_kernel(float* __restrict__ out, int N) {
    float avg = 0.0f;
    for (int n = 0; n < N; n++)
        avg += fmaxf((float)g_poscnt[n], 1.0f);
    float r0 = (float)g_sums[0] / avg;
    float r1 = (float)g_sums[1] / avg;
    float r2 = (float)g_sums[2] / avg;
    out[0] = (isnan(r0) || isinf(r0)) ? 0.0f : r0;
    out[1] = (isnan(r1) || isinf(r1)) ? 0.0f : r1;
    out[2] = (isnan(r2) || isinf(r2)) ? 0.0f : r2;
}

// ---------------- launch ----------------
extern "C" void kernel_launch(void* const* d_in, const int* in_sizes, int n_in,
                              void* d_out, int out_size) {
    const float* y_true     = (const float*)d_in[0];  // N,P,C
    const float* bbox_true  = (const float*)d_in[1];  // N,P,4
    const float* conf_pred  = (const float*)d_in[2];  // N,A,1
    const float* logit_pred = (const float*)d_in[3];  // N,A,C
    const float* bbox_pred  = (const float*)d_in[4];  // N,A,4
    const float* anchors    = (const float*)d_in[5];  // A,4

    const int A = in_sizes[5] / 4;
    const int N = in_sizes[2] / A;
    const int P = in_sizes[1] / (N * 4);
    const int C = in_sizes[0] / (N * P);

    const int NP = N * P;
    int init_blocks = (NP + 255) / 256;
    if (init_blocks < 1) init_blocks = 1;
    init_kernel<<<init_blocks, 256>>>(NP, N);

    dim3 gA((A + BLK_A * KPT - 1) / (BLK_A * KPT), N);
    assign_kernel<<<gA, BLK_A>>>(bbox_true, anchors, N, A, P);

    lowq_kernel<<<(N + 31) / 32, 32>>>(N, A, P);

    dim3 gL((A + BLK_L - 1) / BLK_L, N);
    loss_kernel<<<gL, BLK_L>>>(conf_pred, logit_pred, bbox_pred,
                               bbox_true, y_true, N, A, P, C);

    final_kernel<<<1, 1>>>((float*)d_out, N);
}

// round 8
// speedup vs baseline: 1.5443x; 1.5443x over previous
#include <cuda_runtime.h>
#include <math.h>

// ---------------- constants ----------------
#define EPSL      1e-7f
#define POS_THRF  0.5f
#define NEG_THRF  0.4f
#define ALPHA_F   0.25f
#define K4PI2     0.40528473456935109f   // 4 / pi^2

#define MAX_NA  806400    // N*A = 32*25200
#define MAX_NP  8192      // N*P
#define MAX_N   64
#define PMAX    128

// ---------------- scratch (static, no allocation) ----------------
__device__ int                g_state[MAX_NA];
__device__ int                g_tidx[MAX_NA];
__device__ int                g_poslist[MAX_NA];
__device__ unsigned long long g_gtpacked[MAX_NP];
__device__ int                g_poscnt[MAX_N];
__device__ int                g_npos;
__device__ double             g_sums[3];

// ---------------- kernel 0: zero scratch that needs it ----------------
__global__ void init_kernel(int NP, int N) {
    int i = blockIdx.x * blockDim.x + threadIdx.x;
    if (i < NP) g_gtpacked[i] = 0ull;
    if (i < N)  g_poscnt[i]   = 0;
    if (i < 3)  g_sums[i]     = 0.0;
    if (i == 0) g_npos        = 0;
}

// ---------------- kernel 1: max-IoU assigner ----------------
// 8 anchors per thread, 128 threads/block -> 1024 anchors per block.
#define BLK_A 128
#define KPT   8

__global__ void assign_kernel(const float* __restrict__ bbox_true,
                              const float* __restrict__ anchors,
                              int N, int A, int P) {
    __shared__ float4             gbox[PMAX];
    __shared__ float              gAe[PMAX];     // area + EPS
    __shared__ int                gvalid[PMAX];
    __shared__ short              glist[PMAX];
    __shared__ int                gcnt;
    __shared__ unsigned long long gts[PMAX];

    const int n    = blockIdx.y;
    const int tid  = threadIdx.x;
    const int lane = tid & 31;

    for (int p = tid; p < P; p += BLK_A) {
        float4 b = ((const float4*)bbox_true)[(long)n * P + p];
        gbox[p]   = b;
        gAe[p]    = (b.z - b.x) * (b.w - b.y) + EPSL;
        gvalid[p] = (b.x > 0.f) || (b.y > 0.f) || (b.z > 0.f) || (b.w > 0.f);
        gts[p]    = 0ull;
    }
    __syncthreads();
    // order-preserving compaction (ties in argmax need first-occurrence order)
    if (tid == 0) {
        int c = 0;
        for (int p = 0; p < P; p++) if (gvalid[p]) glist[c++] = (short)p;
        gcnt = c;
    }
    __syncthreads();
    const int cn = gcnt;

    const int abase = blockIdx.x * (BLK_A * KPT) + tid;

    float ax1[KPT], ay1[KPT], ax2[KPT], ay2[KPT], aA[KPT], best[KPT];
    int   bestp[KPT];

#pragma unroll
    for (int k = 0; k < KPT; k++) {
        int a = abase + k * BLK_A;
        best[k]  = -1.0f;
        bestp[k] = 0;
        if (a < A) {
            float4 b = ((const float4*)anchors)[a];
            ax1[k] = b.x; ay1[k] = b.y; ax2[k] = b.z; ay2[k] = b.w;
            aA[k]  = (b.z - b.x) * (b.w - b.y);
        } else {
            // degenerate box: inter=0, area=0 -> iou = 0, never pushed to gt side
            ax1[k] = 4.0f; ay1[k] = 4.0f; ax2[k] = 4.0f; ay2[k] = 4.0f;
            aA[k]  = 0.0f;
        }
    }

    for (int ci = 0; ci < cn; ci++) {
        const int    p  = glist[ci];
        const float4 g  = gbox[p];
        const float  gA = gAe[p];

        float    m  = 0.0f;   // only iou>0 matters for gt side
        unsigned ma = 0u;
#pragma unroll
        for (int k = 0; k < KPT; k++) {
            float iw = fminf(ax2[k], g.z) - fmaxf(ax1[k], g.x);
            float ih = fminf(ay2[k], g.w) - fmaxf(ay1[k], g.y);
            iw = fmaxf(iw, 0.0f); ih = fmaxf(ih, 0.0f);
            float inter = iw * ih;
            float iou = __fdividef(inter, aA[k] + gA - inter);
            if (iou > best[k]) { best[k] = iou; bestp[k] = p; }              // first-occurrence argmax over p
            if (iou > m)       { m = iou; ma = (unsigned)(abase + k * BLK_A); } // smallest anchor idx on tie
        }

        unsigned hi    = __float_as_uint(m);                 // m>=0: bits monotone
        unsigned maxhi = __reduce_max_sync(0xffffffffu, hi);
        if (maxhi) {
            unsigned cand = (hi == maxhi) ? ma : 0xffffffffu;
            unsigned amin = __reduce_min_sync(0xffffffffu, cand);
            if (lane == 0)
                atomicMax(&gts[p], ((unsigned long long)maxhi << 32)
                                 | (unsigned long long)(~amin));  // ~a: bigger => smaller anchor on iou tie
        }
    }
    __syncthreads();

#pragma unroll
    for (int k = 0; k < KPT; k++) {
        int a = abase + k * BLK_A;
        if (a < A) {
            int s = (best[k] >= POS_THRF) ? 1 : ((best[k] < NEG_THRF) ? -1 : 0);
            long idx = (long)n * A + a;
            g_state[idx] = s;
            g_tidx[idx]  = bestp[k];
        }
    }
    for (int p = tid; p < P; p += BLK_A)
        if (gts[p]) atomicMax(&g_gtpacked[(long)n * P + p], gts[p]);
}

// ---------------- kernel 2: low-quality match override ----------------
// one thread per image, serial over p (preserves scatter ordering: last p wins)
__global__ void lowq_kernel(int N, int A, int P) {
    int n = blockIdx.x * blockDim.x + threadIdx.x;
    if (n >= N) return;
    for (int p = 0; p < P; p++) {
        unsigned long long v = g_gtpacked[(long)n * P + p];
        if (v) {  // nonzero => valid gt with gt_max > 0 => lowq
            unsigned a = ~(unsigned)(v & 0xffffffffull);
            long idx = (long)n * A + a;
            g_state[idx] = 1;
            g_tidx[idx]  = p;
        }
    }
}

// ---------------- kernel 3: score loss (streaming, vec4) + positive compaction ----
#define BLK_S 256

__global__ void loss_score_kernel(const float* __restrict__ conf_pred,
                                  int N, int A) {
    const int n    = blockIdx.y;
    const int t    = blockIdx.x * BLK_S + threadIdx.x;
    const int A4   = A >> 2;   // A % 4 == 0 for this problem; groups never straddle
    const int lane = threadIdx.x & 31;

    float score = 0.0f;
    int   cnt   = 0;

    const bool inr  = t < A4;
    const int  base = n * A + t * 4;

    int4   s4 = make_int4(0, 0, 0, 0);
    float4 c4 = make_float4(0.5f, 0.5f, 0.5f, 0.5f);
    if (inr) {
        s4 = *(const int4*)  (g_state   + base);
        c4 = *(const float4*)(conf_pred + base);
    }
    int   ss[4] = { s4.x, s4.y, s4.z, s4.w };
    float cc[4] = { c4.x, c4.y, c4.z, c4.w };

#pragma unroll
    for (int j = 0; j < 4; j++) {
        int s = ss[j];
        if (s) {
            float cp = fminf(fmaxf(cc[j], EPSL), 1.0f - EPSL);
            score += (s == 1) ? -__logf(cp) : -__logf(1.0f - cp);
        }
        bool ispos = (s == 1);
        unsigned msk = __ballot_sync(0xffffffffu, ispos);
        if (msk) {
            int leader = __ffs(msk) - 1;
            int lbase  = 0;
            if (lane == leader) lbase = atomicAdd(&g_npos, __popc(msk));
            lbase = __shfl_sync(0xffffffffu, lbase, leader);
            if (ispos) {
                g_poslist[lbase + __popc(msk & ((1u << lane) - 1))] = base + j;
                cnt++;
            }
        }
    }

    // block reduction
    const int w = threadIdx.x >> 5;
#pragma unroll
    for (int off = 16; off > 0; off >>= 1) {
        score += __shfl_down_sync(0xffffffffu, score, off);
        cnt   += __shfl_down_sync(0xffffffffu, cnt,   off);
    }
    __shared__ float s0[BLK_S / 32];
    __shared__ int   s1[BLK_S / 32];
    if (lane == 0) { s0[w] = score; s1[w] = cnt; }
    __syncthreads();
    if (w == 0) {
        const int nw = BLK_S / 32;
        float v0 = (lane < nw) ? s0[lane] : 0.0f;
        int   v1 = (lane < nw) ? s1[lane] : 0;
#pragma unroll
        for (int off = 16; off > 0; off >>= 1) {
            v0 += __shfl_down_sync(0xffffffffu, v0, off);
            v1 += __shfl_down_sync(0xffffffffu, v1, off);
        }
        if (lane == 0) {
            if (v0 != 0.0f) atomicAdd(&g_sums[0], (double)v0);
            if (v1)         atomicAdd(&g_poscnt[n], v1);
        }
    }
}

// ---------------- kernel 4: per-positive cls (focal) + bbox (CIoU) -----------
// one warp per positive; lanes split the C classes.
#define POS_BLOCKS 132
#define BLK_P      256

__global__ void loss_pos_kernel(const float* __restrict__ logit_pred,
                                const float* __restrict__ bbox_pred,
                                const float* __restrict__ bbox_true,
                                const float* __restrict__ y_true,
                                int A, int P, int C) {
    const int lane   = threadIdx.x & 31;
    const int gw     = (blockIdx.x * BLK_P + threadIdx.x) >> 5;
    const int nwarps = (gridDim.x * BLK_P) >> 5;
    const int cnt    = g_npos;

    float cls = 0.0f, bb = 0.0f;

    for (int i = gw; i < cnt; i += nwarps) {
        const int idx = g_poslist[i];
        const int n   = idx / A;
        const int t   = g_tidx[idx];
        const long trow = (long)n * P + t;

        // CIoU (computed redundantly by all lanes: broadcast loads, no divergence)
        float4 bt = ((const float4*)bbox_true)[trow];
        float4 bp = ((const float4*)bbox_pred)[idx];
        float ix1 = fmaxf(bt.x, bp.x), iy1 = fmaxf(bt.y, bp.y);
        float ix2 = fminf(bt.z, bp.z), iy2 = fminf(bt.w, bp.w);
        float inter = fmaxf(ix2 - ix1, 0.0f) * fmaxf(iy2 - iy1, 0.0f);
        float wt = bt.z - bt.x, ht = bt.w - bt.y;
        float wp = bp.z - bp.x, hp = bp.w - bp.y;
        float uni = wt * ht + wp * hp - inter + EPSL;
        float iou = __fdividef(inter, uni);
        float cw = fmaxf(bt.z, bp.z) - fminf(bt.x, bp.x);
        float ch = fmaxf(bt.w, bp.w) - fminf(bt.y, bp.y);
        float c2 = cw * cw + ch * ch + EPSL;
        float dx = bt.x + bt.z - bp.x - bp.z;
        float dy = bt.y + bt.w - bp.y - bp.w;
        float rho2 = (dx * dx + dy * dy) * 0.25f;
        float da = atanf(__fdividef(wt, ht + EPSL)) - atanf(__fdividef(wp, hp + EPSL));
        float v = K4PI2 * da * da;
        float alpha = __fdividef(v, 1.0f - iou + v + EPSL);
        float ciou = 1.0f - iou + __fdividef(rho2, c2) + alpha * v;
        bb += (lane == 0) ? ciou : 0.0f;

        // focal class loss: lanes stride over C
        const float* lp = logit_pred + (long)idx * C;
        const float* yt = y_true + trow * C;
        for (int c = lane; c < C; c += 32) {
            float q  = fminf(fmaxf(lp[c], EPSL), 1.0f - EPSL);
            float tl = yt[c];
            float pt = tl * q + (1.0f - tl) * (1.0f - q);
            float at = tl * ALPHA_F + (1.0f - tl) * (1.0f - ALPHA_F);
            float om = 1.0f - pt;
            cls += -at * om * om * __logf(pt);
        }
    }

#pragma unroll
    for (int off = 16; off > 0; off >>= 1)
        cls += __shfl_down_sync(0xffffffffu, cls, off);
    if (lane == 0) {
        if (cls != 0.0f) atomicAdd(&g_sums[1], (double)cls);
        if (bb  != 0.0f) atomicAdd(&g_sums[2], (double)bb);
    }
}

// ---------------- kernel 5: finalize ----------------
__global__ void final_kernel(float* __restrict__ out, int N) {
    float avg = 0.0f;
    for (int n = 0; n < N; n++)
        avg += fmaxf((float)g_poscnt[n], 1.0f);
    float r0 = (float)g_sums[0] / avg;
    float r1 = (float)g_sums[1] / avg;
    float r2 = (float)g_sums[2] / avg;
    out[0] = (isnan(r0) || isinf(r0)) ? 0.0f : r0;
    out[1] = (isnan(r1) || isinf(r1)) ? 0.0f : r1;
    out[2] = (isnan(r2) || isinf(r2)) ? 0.0f : r2;
}

// ---------------- launch ----------------
extern "C" void kernel_launch(void* const* d_in, const int* in_sizes, int n_in,
                              void* d_out, int out_size) {
    const float* y_true     = (const float*)d_in[0];  // N,P,C
    const float* bbox_true  = (const float*)d_in[1];  // N,P,4
    const float* conf_pred  = (const float*)d_in[2];  // N,A,1
    const float* logit_pred = (const float*)d_in[3];  // N,A,C
    const float* bbox_pred  = (const float*)d_in[4];  // N,A,4
    const float* anchors    = (const float*)d_in[5];  // A,4

    const int A = in_sizes[5] / 4;
    const int N = in_sizes[2] / A;
    const int P = in_sizes[1] / (N * 4);
    const int C = in_sizes[0] / (N * P);

    const int NP = N * P;
    int init_blocks = (NP + 255) / 256;
    if (init_blocks < 1) init_blocks = 1;
    init_kernel<<<init_blocks, 256>>>(NP, N);

    dim3 gA((A + BLK_A * KPT - 1) / (BLK_A * KPT), N);
    assign_kernel<<<gA, BLK_A>>>(bbox_true, anchors, N, A, P);

    lowq_kernel<<<(N + 31) / 32, 32>>>(N, A, P);

    dim3 gS((A / 4 + BLK_S - 1) / BLK_S, N);
    loss_score_kernel<<<gS, BLK_S>>>(conf_pred, N, A);

    loss_pos_kernel<<<POS_BLOCKS, BLK_P>>>(logit_pred, bbox_pred,
                                           bbox_true, y_true, A, P, C);

    final_kernel<<<1, 1>>>((float*)d_out, N);
}